// round 13
// baseline (speedup 1.0000x reference)
#include <cuda_runtime.h>
#include <cuda_fp16.h>
#include <cstdint>

#define TOK 4096
#define QKV_ELEMS ((size_t)TOK * 6144)

// ---- scratch ----
__device__ float  g_comp[TOK * 8];
__device__ __half g_q[QKV_ELEMS];
__device__ __half g_k[QKV_ELEMS];
__device__ __half g_v[QKV_ELEMS];
__device__ __half g_oh[QKV_ELEMS];        // attention out, fp16
__device__ __half g_xh[4194304];          // x as fp16 [4096][1024]
__device__ __half2 g_wqh[393216];         // packed [8][64 kp][768 e]
__device__ __half2 g_wkh[393216];
__device__ __half2 g_wvh[393216];
__device__ __half2 g_wfh[393216];         // packed [8][384 kp][128 e]

// ============================================================
// helpers
// ============================================================
__device__ __forceinline__ uint32_t smem_u32(const void* p) {
    uint32_t a;
    asm("{ .reg .u64 t; cvta.to.shared.u64 t, %1; cvt.u32.u64 %0, t; }"
        : "=r"(a) : "l"(p));
    return a;
}
__device__ __forceinline__ void cp16(uint32_t dst, const void* src) {
    asm volatile("cp.async.ca.shared.global [%0], [%1], 16;"
                 :: "r"(dst), "l"(src));
}
#define CP_COMMIT() asm volatile("cp.async.commit_group;" ::: "memory")
#define CP_WAIT(n)  asm volatile("cp.async.wait_group %0;" :: "n"(n) : "memory")

__device__ __forceinline__ void mma_f16(float* c, const uint32_t* a,
                                        const uint32_t* b) {
    asm volatile(
        "mma.sync.aligned.m16n8k16.row.col.f32.f16.f16.f32 "
        "{%0,%1,%2,%3}, {%4,%5,%6,%7}, {%8,%9}, {%0,%1,%2,%3};"
        : "+f"(c[0]), "+f"(c[1]), "+f"(c[2]), "+f"(c[3])
        : "r"(a[0]), "r"(a[1]), "r"(a[2]), "r"(a[3]), "r"(b[0]), "r"(b[1]));
}
__device__ __forceinline__ void ldm_x4(uint32_t* r, uint32_t addr) {
    asm volatile(
        "ldmatrix.sync.aligned.m8n8.x4.shared.b16 {%0,%1,%2,%3}, [%4];"
        : "=r"(r[0]), "=r"(r[1]), "=r"(r[2]), "=r"(r[3]) : "r"(addr));
}

// ============================================================
// fused prep: weight fp16 k-pair packs | gating + x->fp16
//   blocks [0, WPK_BLKS): weight packs
//   blocks [WPK_BLKS, WPK_BLKS+512): gating (also writes g_xh)
// ============================================================
#define NWP 98304
#define WPK_BLKS (4 * NWP / 256)   // 1536
#define TOTAL_BLKS (WPK_BLKS + 512)

__global__ void prep_kernel(const float* __restrict__ x,
                            const float* __restrict__ wq,
                            const float* __restrict__ wk,
                            const float* __restrict__ wv,
                            const float* __restrict__ wf,
                            const float* __restrict__ wc) {
    if (blockIdx.x >= WPK_BLKS) {
        // ---- gating + x->fp16 ----
        int gtid = (blockIdx.x - WPK_BLKS) * 256 + threadIdx.x;
        int t    = gtid >> 5;
        int lane = gtid & 31;
        const float* xr = x + (size_t)t * 1024;
        __half* xh = g_xh + (size_t)t * 1024;

        float logit[8];
#pragma unroll
        for (int n = 0; n < 8; n++) {
            const float* xb = xr + n * 128;
            const float* wb = wc + n * 128;
            float v0 = xb[lane],      v1 = xb[lane + 32];
            float v2 = xb[lane + 64], v3 = xb[lane + 96];
            float p = v0 * wb[lane]      + v1 * wb[lane + 32]
                    + v2 * wb[lane + 64] + v3 * wb[lane + 96];
            // fp16 convert of x (fused; same rounding as before)
            xh[n * 128 + lane]      = __float2half_rn(v0);
            xh[n * 128 + lane + 32] = __float2half_rn(v1);
            xh[n * 128 + lane + 64] = __float2half_rn(v2);
            xh[n * 128 + lane + 96] = __float2half_rn(v3);
#pragma unroll
            for (int o = 16; o > 0; o >>= 1)
                p += __shfl_xor_sync(0xffffffffu, p, o);
            logit[n] = p;
        }
        float mx = logit[0];
#pragma unroll
        for (int n = 1; n < 8; n++) mx = fmaxf(mx, logit[n]);
        float s = 0.f, ev = 0.f;
#pragma unroll
        for (int n = 0; n < 8; n++) {
            float e = __expf(logit[n] - mx);
            s += e;
            if (lane == n) ev = e;
        }
        if (lane < 8) g_comp[t * 8 + lane] = ev / s;
        return;
    }

    int u = blockIdx.x * 256 + threadIdx.x;
    const float* w; __half2* o;
    int ldw, kps;
    if (u < NWP)            { w = wq; o = g_wqh; ldw = 768; kps = 64; }
    else if (u < 2 * NWP)   { w = wk; o = g_wkh; ldw = 768; kps = 64; u -= NWP; }
    else if (u < 3 * NWP)   { w = wv; o = g_wvh; ldw = 768; kps = 64; u -= 2 * NWP; }
    else                    { w = wf; o = g_wfh; ldw = 128; kps = 384; u -= 3 * NWP; }
    const int ne4 = ldw / 4;
    int e4 = u % ne4;
    int kp = (u / ne4) % kps;
    int nb = u / (ne4 * kps);
    const float* lo = w + (size_t)nb * 98304 + (size_t)(2 * kp) * ldw + e4 * 4;
    float4 l = *(const float4*)lo;
    float4 h = *(const float4*)(lo + ldw);
    __half2 p[4];
    p[0] = __halves2half2(__float2half_rn(l.x), __float2half_rn(h.x));
    p[1] = __halves2half2(__float2half_rn(l.y), __float2half_rn(h.y));
    p[2] = __halves2half2(__float2half_rn(l.z), __float2half_rn(h.z));
    p[3] = __halves2half2(__float2half_rn(l.w), __float2half_rn(h.w));
    *(uint4*)&o[(size_t)nb * 49152 + (size_t)kp * ldw + e4 * 4] = *(uint4*)p;
}

// ============================================================
// fp16 QKV GEMM: 4-stage full prefetch (unchanged from R12)
// ============================================================
#define QA_W 2560
#define QB_W 2176
#define QSTG_W (QA_W + QB_W)
#define SMEM_Q16 (4 * QSTG_W * 4)  // 75776

__global__ __launch_bounds__(256, 2)
void qkv16_kernel(const __half* __restrict__ Xh,
                  const uint32_t* __restrict__ WQ,
                  const uint32_t* __restrict__ WK,
                  const uint32_t* __restrict__ WV,
                  __half* __restrict__ CQ, __half* __restrict__ CK,
                  __half* __restrict__ CV,
                  const float* __restrict__ comp) {
    extern __shared__ __align__(16) uint32_t smw[];
    const uint32_t sbase = smem_u32(smw);

    const int tid  = threadIdx.x;
    const int wid  = tid >> 5;
    const int lane = tid & 31;
    const int wm   = wid & 3;
    const int wn   = wid >> 2;
    const int g    = lane >> 2;
    const int t    = lane & 3;

    const int mt   = blockIdx.x;
    const int yy   = blockIdx.y;
    const int zb   = blockIdx.z;
    const int mat  = yy / 6;
    const int col0 = (yy % 6) * 128;

    const uint32_t* Wh = (mat == 0 ? WQ : (mat == 1 ? WK : WV)) +
                         (size_t)zb * 49152 + col0;
    __half* C = (mat == 0 ? CQ : (mat == 1 ? CK : CV)) +
                (size_t)zb * 768 + col0;
    const __half* Ah = Xh + (size_t)(mt * 128) * 1024 + zb * 128;

    const uint32_t a_lm = (uint32_t)((wm * 32 + (lane & 15)) * 80 +
                                     (lane >> 4) * 16);

    float acc[2][8][4];
#pragma unroll
    for (int i = 0; i < 2; i++)
#pragma unroll
        for (int j = 0; j < 8; j++)
#pragma unroll
            for (int c = 0; c < 4; c++) acc[i][j][c] = 0.f;

    auto issue_chunk = [&](int kc) {
        const uint32_t ad = sbase + (uint32_t)(kc * QSTG_W) * 4;
        const uint32_t bd = ad + QA_W * 4;
        const int k0h = kc * 32;
#pragma unroll
        for (int p = 0; p < 2; p++) {
            int idx = p * 256 + tid;
            int r = idx >> 2, c16 = idx & 3;
            cp16(ad + (uint32_t)(r * 20 + c16 * 4) * 4,
                 Ah + (size_t)r * 1024 + k0h + c16 * 8);
        }
#pragma unroll
        for (int p = 0; p < 2; p++) {
            int idx = p * 256 + tid;
            int kpl = idx >> 5, c = idx & 31;
            cp16(bd + (uint32_t)(kpl * 136 + c * 4) * 4,
                 Wh + (size_t)(kc * 16 + kpl) * 768 + c * 4);
        }
    };

    issue_chunk(0); CP_COMMIT();
    issue_chunk(1); CP_COMMIT();
    issue_chunk(2); CP_COMMIT();
    issue_chunk(3); CP_COMMIT();

#pragma unroll
    for (int kc = 0; kc < 4; kc++) {
        if (kc == 0)      { CP_WAIT(3); }
        else if (kc == 1) { CP_WAIT(2); }
        else if (kc == 2) { CP_WAIT(1); }
        else              { CP_WAIT(0); }
        __syncthreads();

        const uint32_t* bw = smw + kc * QSTG_W + QA_W;
        const uint32_t a_stage = sbase + (uint32_t)(kc * QSTG_W) * 4 + a_lm;
#pragma unroll
        for (int ks = 0; ks < 2; ks++) {
            uint32_t af[2][4];
#pragma unroll
            for (int i = 0; i < 2; i++)
                ldm_x4(af[i], a_stage + i * 16 * 80 + ks * 32);
            uint32_t bf[8][2];
#pragma unroll
            for (int j = 0; j < 8; j++) {
                const int c = wn * 64 + j * 8 + g;
                bf[j][0] = bw[(ks * 8 + t)     * 136 + c];
                bf[j][1] = bw[(ks * 8 + 4 + t) * 136 + c];
            }
#pragma unroll
            for (int i = 0; i < 2; i++)
#pragma unroll
                for (int j = 0; j < 8; j++)
                    mma_f16(acc[i][j], af[i], bf[j]);
        }
    }

#pragma unroll
    for (int i = 0; i < 2; i++) {
        const int r0 = mt * 128 + wm * 32 + i * 16 + g;
        const int r1 = r0 + 8;
        const float sc0 = comp[r0 * 8 + zb];
        const float sc1 = comp[r1 * 8 + zb];
        __half* Cr0 = C + (size_t)r0 * 6144;
        __half* Cr1 = C + (size_t)r1 * 6144;
#pragma unroll
        for (int j = 0; j < 8; j++) {
            const int c = wn * 64 + j * 8 + 2 * t;
            *(__half2*)(Cr0 + c) =
                __floats2half2_rn(acc[i][j][0] * sc0, acc[i][j][1] * sc0);
            *(__half2*)(Cr1 + c) =
                __floats2half2_rn(acc[i][j][2] * sc1, acc[i][j][3] * sc1);
        }
    }
}

// ============================================================
// fp16 final GEMM: 128 threads, 4 warps (1x4), 4 CTAs/SM,
// single-wave grid. 4-stage pipeline.
// ============================================================
#define FA_W 1280            // 64*20
#define FB_W 2176            // 16*136
#define FSTG_W (FA_W + FB_W) // 3456
#define SMEM_F16 (4 * FSTG_W * 4)  // 55296

__global__ __launch_bounds__(128, 4)
void fin16_kernel(const __half* __restrict__ Oh,
                  const uint32_t* __restrict__ WF,
                  float* __restrict__ out) {
    extern __shared__ __align__(16) uint32_t smw[];
    const uint32_t sbase = smem_u32(smw);

    const int tid  = threadIdx.x;
    const int wn   = tid >> 5;      // warp col (0..3)
    const int lane = tid & 31;
    const int g    = lane >> 2;
    const int t    = lane & 3;

    const int mt = blockIdx.x;
    const int zb = blockIdx.z;

    const uint32_t* Wh = WF + (size_t)zb * 49152;
    const __half* Ah = Oh + (size_t)(mt * 64) * 6144 + zb * 768;
    float* C = out + (size_t)zb * 128;

    const uint32_t a_lm = (uint32_t)(((lane & 15)) * 80 + (lane >> 4) * 16);

    float acc[4][4][4];
#pragma unroll
    for (int i = 0; i < 4; i++)
#pragma unroll
        for (int j = 0; j < 4; j++)
#pragma unroll
            for (int c = 0; c < 4; c++) acc[i][j][c] = 0.f;

    auto issue_chunk = [&](int kc) {
        const int st = kc & 3;
        const uint32_t ad = sbase + (uint32_t)(st * FSTG_W) * 4;
        const uint32_t bd = ad + FA_W * 4;
        // A: 64 rows x 4 c16 = 256 cp16, 2/thread
#pragma unroll
        for (int p = 0; p < 2; p++) {
            int idx = p * 128 + tid;
            int r = idx >> 2, c16 = idx & 3;
            cp16(ad + (uint32_t)(r * 20 + c16 * 4) * 4,
                 Ah + (size_t)r * 6144 + kc * 32 + c16 * 8);
        }
        // B: 16 kp x 32 c = 512 cp16, 4/thread
#pragma unroll
        for (int p = 0; p < 4; p++) {
            int idx = p * 128 + tid;
            int kpl = idx >> 5, c = idx & 31;
            cp16(bd + (uint32_t)(kpl * 136 + c * 4) * 4,
                 Wh + (size_t)(kc * 16 + kpl) * 128 + c * 4);
        }
    };

    // prologue: 3 chunks in flight
    issue_chunk(0); CP_COMMIT();
    issue_chunk(1); CP_COMMIT();
    issue_chunk(2); CP_COMMIT();

    for (int kc = 0; kc < 24; kc++) {
        if (kc < 22)      { CP_WAIT(2); }
        else if (kc == 22){ CP_WAIT(1); }
        else              { CP_WAIT(0); }
        __syncthreads();
        if (kc + 3 < 24) { issue_chunk(kc + 3); CP_COMMIT(); }

        const uint32_t* bw = smw + (kc & 3) * FSTG_W + FA_W;
        const uint32_t a_stage = sbase + (uint32_t)((kc & 3) * FSTG_W) * 4 + a_lm;
#pragma unroll
        for (int ks = 0; ks < 2; ks++) {
            uint32_t af[4][4];
#pragma unroll
            for (int i = 0; i < 4; i++)
                ldm_x4(af[i], a_stage + i * 16 * 80 + ks * 32);
            uint32_t bf[4][2];
#pragma unroll
            for (int j = 0; j < 4; j++) {
                const int c = wn * 32 + j * 8 + g;
                bf[j][0] = bw[(ks * 8 + t)     * 136 + c];
                bf[j][1] = bw[(ks * 8 + 4 + t) * 136 + c];
            }
#pragma unroll
            for (int i = 0; i < 4; i++)
#pragma unroll
                for (int j = 0; j < 4; j++)
                    mma_f16(acc[i][j], af[i], bf[j]);
        }
    }

#pragma unroll
    for (int i = 0; i < 4; i++) {
        const int r0 = mt * 64 + i * 16 + g;
        const int r1 = r0 + 8;
        float* Cr0 = C + (size_t)r0 * 1024;
        float* Cr1 = C + (size_t)r1 * 1024;
#pragma unroll
        for (int j = 0; j < 4; j++) {
            const int c = wn * 32 + j * 8 + 2 * t;
            *(float2*)(Cr0 + c) = make_float2(acc[i][j][0], acc[i][j][1]);
            *(float2*)(Cr1 + c) = make_float2(acc[i][j][2], acc[i][j][3]);
        }
    }
}

// ============================================================
// Kernel C: register/shuffle block-attention (unchanged)
// ============================================================
__global__ __launch_bounds__(384, 2)
void attn_kernel(float* __restrict__ out) {
    __shared__ float ss[12 * 64];

    const int t    = blockIdx.x;
    const int tid  = threadIdx.x;
    const int w    = tid >> 5;
    const int lane = tid & 31;
    const int n    = lane >> 2;
    const int p    = lane & 3;

    const size_t base = (size_t)t * 6144 + (size_t)n * 768 + w * 64 + p * 16;

    uint4 qa = *(const uint4*)(g_q + base);
    uint4 qb = *(const uint4*)(g_q + base + 8);
    uint4 ka = *(const uint4*)(g_k + base);
    uint4 kb = *(const uint4*)(g_k + base + 8);
    uint4 va = *(const uint4*)(g_v + base);
    uint4 vb = *(const uint4*)(g_v + base + 8);

    uint32_t kh[8] = {ka.x, ka.y, ka.z, ka.w, kb.x, kb.y, kb.z, kb.w};
    uint32_t vh[8] = {va.x, va.y, va.z, va.w, vb.x, vb.y, vb.z, vb.w};

    float qf[16];
    {
        const uint32_t qh[8] = {qa.x, qa.y, qa.z, qa.w, qb.x, qb.y, qb.z, qb.w};
#pragma unroll
        for (int r = 0; r < 8; r++) {
            float2 f = __half22float2(*(const __half2*)&qh[r]);
            qf[2 * r]     = f.x;
            qf[2 * r + 1] = f.y;
        }
    }

    float sc[8];
#pragma unroll
    for (int m = 0; m < 8; m++) {
        const int src = m * 4 + p;
        float a = 0.f;
#pragma unroll
        for (int r = 0; r < 8; r++) {
            uint32_t kk = __shfl_sync(0xffffffffu, kh[r], src);
            float2 f = __half22float2(*(const __half2*)&kk);
            a = fmaf(qf[2 * r], f.x, a);
            a = fmaf(qf[2 * r + 1], f.y, a);
        }
        sc[m] = a;
    }
#pragma unroll
    for (int o = 1; o <= 2; o <<= 1)
#pragma unroll
        for (int m = 0; m < 8; m++)
            sc[m] += __shfl_xor_sync(0xffffffffu, sc[m], o);
#pragma unroll
    for (int m = 0; m < 8; m++) sc[m] *= 0.125f;

    float mx = sc[0];
#pragma unroll
    for (int m = 1; m < 8; m++) mx = fmaxf(mx, sc[m]);
    float den = 0.f;
#pragma unroll
    for (int m = 0; m < 8; m++) { sc[m] = __expf(sc[m] - mx); den += sc[m]; }
    const float inv = 1.0f / den;
#pragma unroll
    for (int m = 0; m < 8; m++) sc[m] *= inv;

    if (p == 0) {
#pragma unroll
        for (int m = 0; m < 8; m++) ss[w * 64 + n * 8 + m] = sc[m];
    }

    float of[16];
#pragma unroll
    for (int r = 0; r < 16; r++) of[r] = 0.f;
#pragma unroll
    for (int m = 0; m < 8; m++) {
        const int src = m * 4 + p;
        const float a = sc[m];
#pragma unroll
        for (int r = 0; r < 8; r++) {
            uint32_t vv = __shfl_sync(0xffffffffu, vh[r], src);
            float2 f = __half22float2(*(const __half2*)&vv);
            of[2 * r]     = fmaf(a, f.x, of[2 * r]);
            of[2 * r + 1] = fmaf(a, f.y, of[2 * r + 1]);
        }
    }
    __half2 oh[8];
#pragma unroll
    for (int r = 0; r < 8; r++)
        oh[r] = __floats2half2_rn(of[2 * r], of[2 * r + 1]);
    __half* dst = g_oh + base;
    *(uint4*)dst       = *(uint4*)&oh[0];
    *(uint4*)(dst + 8) = *(uint4*)&oh[4];

    __syncthreads();
    if (tid < 64) {
        float sum = 0.f;
#pragma unroll
        for (int h = 0; h < 12; h++) sum += ss[h * 64 + tid];
        out[4194304 + (size_t)t * 64 + tid] = sum * (1.0f / 12.0f);
    }
}

// ============================================================
// launch
// ============================================================
extern "C" void kernel_launch(void* const* d_in, const int* in_sizes, int n_in,
                              void* d_out, int out_size) {
    const float* x  = (const float*)d_in[0];
    const float* wc = (const float*)d_in[1];
    const float* wq = (const float*)d_in[2];
    const float* wk = (const float*)d_in[3];
    const float* wv = (const float*)d_in[4];
    const float* wf = (const float*)d_in[5];
    float* out = (float*)d_out;

    __half *gq, *gk, *gv, *goh, *gxh;
    __half2 *gwqh, *gwkh, *gwvh, *gwfh;
    float *gc;
    cudaGetSymbolAddress((void**)&gq, g_q);
    cudaGetSymbolAddress((void**)&gk, g_k);
    cudaGetSymbolAddress((void**)&gv, g_v);
    cudaGetSymbolAddress((void**)&goh, g_oh);
    cudaGetSymbolAddress((void**)&gc, g_comp);
    cudaGetSymbolAddress((void**)&gxh, g_xh);
    cudaGetSymbolAddress((void**)&gwqh, g_wqh);
    cudaGetSymbolAddress((void**)&gwkh, g_wkh);
    cudaGetSymbolAddress((void**)&gwvh, g_wvh);
    cudaGetSymbolAddress((void**)&gwfh, g_wfh);

    cudaFuncSetAttribute(qkv16_kernel,
                         cudaFuncAttributeMaxDynamicSharedMemorySize, SMEM_Q16);
    cudaFuncSetAttribute(fin16_kernel,
                         cudaFuncAttributeMaxDynamicSharedMemorySize, SMEM_F16);

    // fused prep (weight packs) + gating+x->fp16, one launch
    prep_kernel<<<TOTAL_BLKS, 256>>>(x, wq, wk, wv, wf, wc);

    // B: fp16 QKV GEMMs. 18 = 3 mats x 6 col-tiles of 128.
    dim3 gB(32, 18, 8);
    qkv16_kernel<<<gB, 256, SMEM_Q16>>>(
        gxh, (const uint32_t*)gwqh, (const uint32_t*)gwkh,
        (const uint32_t*)gwvh, gq, gk, gv, gc);

    // C: register/shuffle attention + score_mean (fp16 out)
    attn_kernel<<<TOK, 384>>>(out);

    // D: fp16 final GEMM, 4 warps / 4 CTAs-SM, single wave.
    dim3 gD(64, 1, 8);
    fin16_kernel<<<gD, 128, SMEM_F16>>>(goh, (const uint32_t*)gwfh, out);
}

// round 14
// speedup vs baseline: 1.0404x; 1.0404x over previous
#include <cuda_runtime.h>
#include <cuda_fp16.h>
#include <cstdint>

#define TOK 4096
#define QKV_ELEMS ((size_t)TOK * 6144)

// ---- scratch ----
__device__ float  g_comp[TOK * 8];
__device__ __half g_q[QKV_ELEMS];
__device__ __half g_k[QKV_ELEMS];
__device__ __half g_v[QKV_ELEMS];
__device__ __half g_oh[QKV_ELEMS];        // attention out, fp16
__device__ __half g_xh[4194304];          // x as fp16 [4096][1024]
__device__ __half2 g_wqh[393216];         // packed [8][64 kp][768 e]
__device__ __half2 g_wkh[393216];
__device__ __half2 g_wvh[393216];
__device__ __half2 g_wfh[393216];         // packed [8][384 kp][128 e]

// ============================================================
// helpers
// ============================================================
__device__ __forceinline__ uint32_t smem_u32(const void* p) {
    uint32_t a;
    asm("{ .reg .u64 t; cvta.to.shared.u64 t, %1; cvt.u32.u64 %0, t; }"
        : "=r"(a) : "l"(p));
    return a;
}
__device__ __forceinline__ void cp16(uint32_t dst, const void* src) {
    asm volatile("cp.async.ca.shared.global [%0], [%1], 16;"
                 :: "r"(dst), "l"(src));
}
#define CP_COMMIT() asm volatile("cp.async.commit_group;" ::: "memory")
#define CP_WAIT(n)  asm volatile("cp.async.wait_group %0;" :: "n"(n) : "memory")

__device__ __forceinline__ void mma_f16(float* c, const uint32_t* a,
                                        const uint32_t* b) {
    asm volatile(
        "mma.sync.aligned.m16n8k16.row.col.f32.f16.f16.f32 "
        "{%0,%1,%2,%3}, {%4,%5,%6,%7}, {%8,%9}, {%0,%1,%2,%3};"
        : "+f"(c[0]), "+f"(c[1]), "+f"(c[2]), "+f"(c[3])
        : "r"(a[0]), "r"(a[1]), "r"(a[2]), "r"(a[3]), "r"(b[0]), "r"(b[1]));
}
__device__ __forceinline__ void ldm_x4(uint32_t* r, uint32_t addr) {
    asm volatile(
        "ldmatrix.sync.aligned.m8n8.x4.shared.b16 {%0,%1,%2,%3}, [%4];"
        : "=r"(r[0]), "=r"(r[1]), "=r"(r[2]), "=r"(r[3]) : "r"(addr));
}

// ============================================================
// fused prep: weight fp16 k-pair packs | gating + x->fp16
// ============================================================
#define NWP 98304
#define WPK_BLKS (4 * NWP / 256)   // 1536
#define TOTAL_BLKS (WPK_BLKS + 512)

__global__ void prep_kernel(const float* __restrict__ x,
                            const float* __restrict__ wq,
                            const float* __restrict__ wk,
                            const float* __restrict__ wv,
                            const float* __restrict__ wf,
                            const float* __restrict__ wc) {
    if (blockIdx.x >= WPK_BLKS) {
        // ---- gating + x->fp16 ----
        int gtid = (blockIdx.x - WPK_BLKS) * 256 + threadIdx.x;
        int t    = gtid >> 5;
        int lane = gtid & 31;
        const float* xr = x + (size_t)t * 1024;
        __half* xh = g_xh + (size_t)t * 1024;

        float logit[8];
#pragma unroll
        for (int n = 0; n < 8; n++) {
            const float* xb = xr + n * 128;
            const float* wb = wc + n * 128;
            float v0 = xb[lane],      v1 = xb[lane + 32];
            float v2 = xb[lane + 64], v3 = xb[lane + 96];
            float p = v0 * wb[lane]      + v1 * wb[lane + 32]
                    + v2 * wb[lane + 64] + v3 * wb[lane + 96];
            xh[n * 128 + lane]      = __float2half_rn(v0);
            xh[n * 128 + lane + 32] = __float2half_rn(v1);
            xh[n * 128 + lane + 64] = __float2half_rn(v2);
            xh[n * 128 + lane + 96] = __float2half_rn(v3);
#pragma unroll
            for (int o = 16; o > 0; o >>= 1)
                p += __shfl_xor_sync(0xffffffffu, p, o);
            logit[n] = p;
        }
        float mx = logit[0];
#pragma unroll
        for (int n = 1; n < 8; n++) mx = fmaxf(mx, logit[n]);
        float s = 0.f, ev = 0.f;
#pragma unroll
        for (int n = 0; n < 8; n++) {
            float e = __expf(logit[n] - mx);
            s += e;
            if (lane == n) ev = e;
        }
        if (lane < 8) g_comp[t * 8 + lane] = ev / s;
        return;
    }

    int u = blockIdx.x * 256 + threadIdx.x;
    const float* w; __half2* o;
    int ldw, kps;
    if (u < NWP)            { w = wq; o = g_wqh; ldw = 768; kps = 64; }
    else if (u < 2 * NWP)   { w = wk; o = g_wkh; ldw = 768; kps = 64; u -= NWP; }
    else if (u < 3 * NWP)   { w = wv; o = g_wvh; ldw = 768; kps = 64; u -= 2 * NWP; }
    else                    { w = wf; o = g_wfh; ldw = 128; kps = 384; u -= 3 * NWP; }
    const int ne4 = ldw / 4;
    int e4 = u % ne4;
    int kp = (u / ne4) % kps;
    int nb = u / (ne4 * kps);
    const float* lo = w + (size_t)nb * 98304 + (size_t)(2 * kp) * ldw + e4 * 4;
    float4 l = *(const float4*)lo;
    float4 h = *(const float4*)(lo + ldw);
    __half2 p[4];
    p[0] = __halves2half2(__float2half_rn(l.x), __float2half_rn(h.x));
    p[1] = __halves2half2(__float2half_rn(l.y), __float2half_rn(h.y));
    p[2] = __halves2half2(__float2half_rn(l.z), __float2half_rn(h.z));
    p[3] = __halves2half2(__float2half_rn(l.w), __float2half_rn(h.w));
    *(uint4*)&o[(size_t)nb * 49152 + (size_t)kp * ldw + e4 * 4] = *(uint4*)p;
}

// ============================================================
// fp16 QKV GEMM: 4-stage full prefetch (unchanged from R12)
// ============================================================
#define QA_W 2560
#define QB_W 2176
#define QSTG_W (QA_W + QB_W)
#define SMEM_Q16 (4 * QSTG_W * 4)  // 75776

__global__ __launch_bounds__(256, 2)
void qkv16_kernel(const __half* __restrict__ Xh,
                  const uint32_t* __restrict__ WQ,
                  const uint32_t* __restrict__ WK,
                  const uint32_t* __restrict__ WV,
                  __half* __restrict__ CQ, __half* __restrict__ CK,
                  __half* __restrict__ CV,
                  const float* __restrict__ comp) {
    extern __shared__ __align__(16) uint32_t smw[];
    const uint32_t sbase = smem_u32(smw);

    const int tid  = threadIdx.x;
    const int wid  = tid >> 5;
    const int lane = tid & 31;
    const int wm   = wid & 3;
    const int wn   = wid >> 2;
    const int g    = lane >> 2;
    const int t    = lane & 3;

    const int mt   = blockIdx.x;
    const int yy   = blockIdx.y;
    const int zb   = blockIdx.z;
    const int mat  = yy / 6;
    const int col0 = (yy % 6) * 128;

    const uint32_t* Wh = (mat == 0 ? WQ : (mat == 1 ? WK : WV)) +
                         (size_t)zb * 49152 + col0;
    __half* C = (mat == 0 ? CQ : (mat == 1 ? CK : CV)) +
                (size_t)zb * 768 + col0;
    const __half* Ah = Xh + (size_t)(mt * 128) * 1024 + zb * 128;

    const uint32_t a_lm = (uint32_t)((wm * 32 + (lane & 15)) * 80 +
                                     (lane >> 4) * 16);

    float acc[2][8][4];
#pragma unroll
    for (int i = 0; i < 2; i++)
#pragma unroll
        for (int j = 0; j < 8; j++)
#pragma unroll
            for (int c = 0; c < 4; c++) acc[i][j][c] = 0.f;

    auto issue_chunk = [&](int kc) {
        const uint32_t ad = sbase + (uint32_t)(kc * QSTG_W) * 4;
        const uint32_t bd = ad + QA_W * 4;
        const int k0h = kc * 32;
#pragma unroll
        for (int p = 0; p < 2; p++) {
            int idx = p * 256 + tid;
            int r = idx >> 2, c16 = idx & 3;
            cp16(ad + (uint32_t)(r * 20 + c16 * 4) * 4,
                 Ah + (size_t)r * 1024 + k0h + c16 * 8);
        }
#pragma unroll
        for (int p = 0; p < 2; p++) {
            int idx = p * 256 + tid;
            int kpl = idx >> 5, c = idx & 31;
            cp16(bd + (uint32_t)(kpl * 136 + c * 4) * 4,
                 Wh + (size_t)(kc * 16 + kpl) * 768 + c * 4);
        }
    };

    issue_chunk(0); CP_COMMIT();
    issue_chunk(1); CP_COMMIT();
    issue_chunk(2); CP_COMMIT();
    issue_chunk(3); CP_COMMIT();

#pragma unroll
    for (int kc = 0; kc < 4; kc++) {
        if (kc == 0)      { CP_WAIT(3); }
        else if (kc == 1) { CP_WAIT(2); }
        else if (kc == 2) { CP_WAIT(1); }
        else              { CP_WAIT(0); }
        __syncthreads();

        const uint32_t* bw = smw + kc * QSTG_W + QA_W;
        const uint32_t a_stage = sbase + (uint32_t)(kc * QSTG_W) * 4 + a_lm;
#pragma unroll
        for (int ks = 0; ks < 2; ks++) {
            uint32_t af[2][4];
#pragma unroll
            for (int i = 0; i < 2; i++)
                ldm_x4(af[i], a_stage + i * 16 * 80 + ks * 32);
            uint32_t bf[8][2];
#pragma unroll
            for (int j = 0; j < 8; j++) {
                const int c = wn * 64 + j * 8 + g;
                bf[j][0] = bw[(ks * 8 + t)     * 136 + c];
                bf[j][1] = bw[(ks * 8 + 4 + t) * 136 + c];
            }
#pragma unroll
            for (int i = 0; i < 2; i++)
#pragma unroll
                for (int j = 0; j < 8; j++)
                    mma_f16(acc[i][j], af[i], bf[j]);
        }
    }

#pragma unroll
    for (int i = 0; i < 2; i++) {
        const int r0 = mt * 128 + wm * 32 + i * 16 + g;
        const int r1 = r0 + 8;
        const float sc0 = comp[r0 * 8 + zb];
        const float sc1 = comp[r1 * 8 + zb];
        __half* Cr0 = C + (size_t)r0 * 6144;
        __half* Cr1 = C + (size_t)r1 * 6144;
#pragma unroll
        for (int j = 0; j < 8; j++) {
            const int c = wn * 64 + j * 8 + 2 * t;
            *(__half2*)(Cr0 + c) =
                __floats2half2_rn(acc[i][j][0] * sc0, acc[i][j][1] * sc0);
            *(__half2*)(Cr1 + c) =
                __floats2half2_rn(acc[i][j][2] * sc1, acc[i][j][3] * sc1);
        }
    }
}

// ============================================================
// fp16 final GEMM: qkv16 shape (MT=128, 256 thr, 8 warps 4x2),
// KC=24, 4-stage circular pipeline, single-wave grid (256 CTAs).
// ============================================================
#define FA_W 2560            // 128*20
#define FB_W 2176            // 16*136
#define FSTG_W (FA_W + FB_W) // 4736
#define SMEM_F16 (4 * FSTG_W * 4)  // 75776

__global__ __launch_bounds__(256, 2)
void fin16_kernel(const __half* __restrict__ Oh,
                  const uint32_t* __restrict__ WF,
                  float* __restrict__ out) {
    extern __shared__ __align__(16) uint32_t smw[];
    const uint32_t sbase = smem_u32(smw);

    const int tid  = threadIdx.x;
    const int wid  = tid >> 5;
    const int lane = tid & 31;
    const int wm   = wid & 3;
    const int wn   = wid >> 2;
    const int g    = lane >> 2;
    const int t    = lane & 3;

    const int mt = blockIdx.x;
    const int zb = blockIdx.z;

    const uint32_t* Wh = WF + (size_t)zb * 49152;
    const __half* Ah = Oh + (size_t)(mt * 128) * 6144 + zb * 768;
    float* C = out + (size_t)zb * 128;

    const uint32_t a_lm = (uint32_t)((wm * 32 + (lane & 15)) * 80 +
                                     (lane >> 4) * 16);

    float acc[2][8][4];
#pragma unroll
    for (int i = 0; i < 2; i++)
#pragma unroll
        for (int j = 0; j < 8; j++)
#pragma unroll
            for (int c = 0; c < 4; c++) acc[i][j][c] = 0.f;

    auto issue_chunk = [&](int kc) {
        const int st = kc & 3;
        const uint32_t ad = sbase + (uint32_t)(st * FSTG_W) * 4;
        const uint32_t bd = ad + FA_W * 4;
        // A: 128 rows x 4 c16 = 512 cp16, 2/thread
#pragma unroll
        for (int p = 0; p < 2; p++) {
            int idx = p * 256 + tid;
            int r = idx >> 2, c16 = idx & 3;
            cp16(ad + (uint32_t)(r * 20 + c16 * 4) * 4,
                 Ah + (size_t)r * 6144 + kc * 32 + c16 * 8);
        }
        // B: 16 kp x 32 c = 512 cp16, 2/thread. NT=128 covers full wf width.
#pragma unroll
        for (int p = 0; p < 2; p++) {
            int idx = p * 256 + tid;
            int kpl = idx >> 5, c = idx & 31;
            cp16(bd + (uint32_t)(kpl * 136 + c * 4) * 4,
                 Wh + (size_t)(kc * 16 + kpl) * 128 + c * 4);
        }
    };

    // prologue: 3 chunks in flight
    issue_chunk(0); CP_COMMIT();
    issue_chunk(1); CP_COMMIT();
    issue_chunk(2); CP_COMMIT();

    for (int kc = 0; kc < 24; kc++) {
        if (kc < 22)      { CP_WAIT(2); }
        else if (kc == 22){ CP_WAIT(1); }
        else              { CP_WAIT(0); }
        __syncthreads();
        if (kc + 3 < 24) { issue_chunk(kc + 3); CP_COMMIT(); }

        const uint32_t* bw = smw + (kc & 3) * FSTG_W + FA_W;
        const uint32_t a_stage = sbase + (uint32_t)((kc & 3) * FSTG_W) * 4 + a_lm;
#pragma unroll
        for (int ks = 0; ks < 2; ks++) {
            uint32_t af[2][4];
#pragma unroll
            for (int i = 0; i < 2; i++)
                ldm_x4(af[i], a_stage + i * 16 * 80 + ks * 32);
            uint32_t bf[8][2];
#pragma unroll
            for (int j = 0; j < 8; j++) {
                const int c = wn * 64 + j * 8 + g;
                bf[j][0] = bw[(ks * 8 + t)     * 136 + c];
                bf[j][1] = bw[(ks * 8 + 4 + t) * 136 + c];
            }
#pragma unroll
            for (int i = 0; i < 2; i++)
#pragma unroll
                for (int j = 0; j < 8; j++)
                    mma_f16(acc[i][j], af[i], bf[j]);
        }
    }

#pragma unroll
    for (int i = 0; i < 2; i++) {
        const int r0 = mt * 128 + wm * 32 + i * 16 + g;
        const int r1 = r0 + 8;
        float* Cr0 = C + (size_t)r0 * 1024;
        float* Cr1 = C + (size_t)r1 * 1024;
#pragma unroll
        for (int j = 0; j < 8; j++) {
            const int c = wn * 64 + j * 8 + 2 * t;
            *(float2*)(Cr0 + c) = make_float2(acc[i][j][0], acc[i][j][1]);
            *(float2*)(Cr1 + c) = make_float2(acc[i][j][2], acc[i][j][3]);
        }
    }
}

// ============================================================
// Kernel C: register/shuffle block-attention (unchanged)
// ============================================================
__global__ __launch_bounds__(384, 2)
void attn_kernel(float* __restrict__ out) {
    __shared__ float ss[12 * 64];

    const int t    = blockIdx.x;
    const int tid  = threadIdx.x;
    const int w    = tid >> 5;
    const int lane = tid & 31;
    const int n    = lane >> 2;
    const int p    = lane & 3;

    const size_t base = (size_t)t * 6144 + (size_t)n * 768 + w * 64 + p * 16;

    uint4 qa = *(const uint4*)(g_q + base);
    uint4 qb = *(const uint4*)(g_q + base + 8);
    uint4 ka = *(const uint4*)(g_k + base);
    uint4 kb = *(const uint4*)(g_k + base + 8);
    uint4 va = *(const uint4*)(g_v + base);
    uint4 vb = *(const uint4*)(g_v + base + 8);

    uint32_t kh[8] = {ka.x, ka.y, ka.z, ka.w, kb.x, kb.y, kb.z, kb.w};
    uint32_t vh[8] = {va.x, va.y, va.z, va.w, vb.x, vb.y, vb.z, vb.w};

    float qf[16];
    {
        const uint32_t qh[8] = {qa.x, qa.y, qa.z, qa.w, qb.x, qb.y, qb.z, qb.w};
#pragma unroll
        for (int r = 0; r < 8; r++) {
            float2 f = __half22float2(*(const __half2*)&qh[r]);
            qf[2 * r]     = f.x;
            qf[2 * r + 1] = f.y;
        }
    }

    float sc[8];
#pragma unroll
    for (int m = 0; m < 8; m++) {
        const int src = m * 4 + p;
        float a = 0.f;
#pragma unroll
        for (int r = 0; r < 8; r++) {
            uint32_t kk = __shfl_sync(0xffffffffu, kh[r], src);
            float2 f = __half22float2(*(const __half2*)&kk);
            a = fmaf(qf[2 * r], f.x, a);
            a = fmaf(qf[2 * r + 1], f.y, a);
        }
        sc[m] = a;
    }
#pragma unroll
    for (int o = 1; o <= 2; o <<= 1)
#pragma unroll
        for (int m = 0; m < 8; m++)
            sc[m] += __shfl_xor_sync(0xffffffffu, sc[m], o);
#pragma unroll
    for (int m = 0; m < 8; m++) sc[m] *= 0.125f;

    float mx = sc[0];
#pragma unroll
    for (int m = 1; m < 8; m++) mx = fmaxf(mx, sc[m]);
    float den = 0.f;
#pragma unroll
    for (int m = 0; m < 8; m++) { sc[m] = __expf(sc[m] - mx); den += sc[m]; }
    const float inv = 1.0f / den;
#pragma unroll
    for (int m = 0; m < 8; m++) sc[m] *= inv;

    if (p == 0) {
#pragma unroll
        for (int m = 0; m < 8; m++) ss[w * 64 + n * 8 + m] = sc[m];
    }

    float of[16];
#pragma unroll
    for (int r = 0; r < 16; r++) of[r] = 0.f;
#pragma unroll
    for (int m = 0; m < 8; m++) {
        const int src = m * 4 + p;
        const float a = sc[m];
#pragma unroll
        for (int r = 0; r < 8; r++) {
            uint32_t vv = __shfl_sync(0xffffffffu, vh[r], src);
            float2 f = __half22float2(*(const __half2*)&vv);
            of[2 * r]     = fmaf(a, f.x, of[2 * r]);
            of[2 * r + 1] = fmaf(a, f.y, of[2 * r + 1]);
        }
    }
    __half2 oh[8];
#pragma unroll
    for (int r = 0; r < 8; r++)
        oh[r] = __floats2half2_rn(of[2 * r], of[2 * r + 1]);
    __half* dst = g_oh + base;
    *(uint4*)dst       = *(uint4*)&oh[0];
    *(uint4*)(dst + 8) = *(uint4*)&oh[4];

    __syncthreads();
    if (tid < 64) {
        float sum = 0.f;
#pragma unroll
        for (int h = 0; h < 12; h++) sum += ss[h * 64 + tid];
        out[4194304 + (size_t)t * 64 + tid] = sum * (1.0f / 12.0f);
    }
}

// ============================================================
// launch
// ============================================================
extern "C" void kernel_launch(void* const* d_in, const int* in_sizes, int n_in,
                              void* d_out, int out_size) {
    const float* x  = (const float*)d_in[0];
    const float* wc = (const float*)d_in[1];
    const float* wq = (const float*)d_in[2];
    const float* wk = (const float*)d_in[3];
    const float* wv = (const float*)d_in[4];
    const float* wf = (const float*)d_in[5];
    float* out = (float*)d_out;

    __half *gq, *gk, *gv, *goh, *gxh;
    __half2 *gwqh, *gwkh, *gwvh, *gwfh;
    float *gc;
    cudaGetSymbolAddress((void**)&gq, g_q);
    cudaGetSymbolAddress((void**)&gk, g_k);
    cudaGetSymbolAddress((void**)&gv, g_v);
    cudaGetSymbolAddress((void**)&goh, g_oh);
    cudaGetSymbolAddress((void**)&gc, g_comp);
    cudaGetSymbolAddress((void**)&gxh, g_xh);
    cudaGetSymbolAddress((void**)&gwqh, g_wqh);
    cudaGetSymbolAddress((void**)&gwkh, g_wkh);
    cudaGetSymbolAddress((void**)&gwvh, g_wvh);
    cudaGetSymbolAddress((void**)&gwfh, g_wfh);

    cudaFuncSetAttribute(qkv16_kernel,
                         cudaFuncAttributeMaxDynamicSharedMemorySize, SMEM_Q16);
    cudaFuncSetAttribute(fin16_kernel,
                         cudaFuncAttributeMaxDynamicSharedMemorySize, SMEM_F16);

    // fused prep (weight packs) + gating+x->fp16, one launch
    prep_kernel<<<TOTAL_BLKS, 256>>>(x, wq, wk, wv, wf, wc);

    // B: fp16 QKV GEMMs. 18 = 3 mats x 6 col-tiles of 128.
    dim3 gB(32, 18, 8);
    qkv16_kernel<<<gB, 256, SMEM_Q16>>>(
        gxh, (const uint32_t*)gwqh, (const uint32_t*)gwkh,
        (const uint32_t*)gwvh, gq, gk, gv, gc);

    // C: register/shuffle attention + score_mean (fp16 out)
    attn_kernel<<<TOK, 384>>>(out);

    // D: fp16 final GEMM, MT=128 single-wave grid (256 CTAs).
    dim3 gD(32, 1, 8);
    fin16_kernel<<<gD, 256, SMEM_F16>>>(goh, (const uint32_t*)gwfh, out);
}